// round 1
// baseline (speedup 1.0000x reference)
#include <cuda_runtime.h>

// ---------------- problem constants ----------------
#define Nn    20000
#define N1c   6000
#define N2c   6000
#define Rr    3
#define Ee    200000
#define HIDc  128
#define NDIMc 64
#define D1c   64
#define D2c   32
#define H1c   4
#define H2c   2
#define Sc    2

// ---------------- device scratch (no allocs allowed) ----------------
__device__ int   g_deg[Rr * Nn];
__device__ int   g_cur[Rr * Nn];
__device__ int   g_ptr[Rr * (Nn + 1)];
__device__ int   g_csrc[Rr * Ee];
__device__ float g_h[(size_t)Rr * Nn * 256];     // per-relation GEMM output (max width 256)
__device__ float g_el[Rr * Nn * H1c];
__device__ float g_er[Rr * Nn * H1c];
__device__ float g_hiddenx[Nn * D1c];
__device__ float g_hidden1[Sc * Nn * D1c];

// ---------------- CSR build ----------------
__global__ void k_zero_deg() {
    int i = blockIdx.x * blockDim.x + threadIdx.x;
    if (i < Rr * Nn) g_deg[i] = 0;
}

__global__ void k_hist(const int* __restrict__ dst) {
    int idx = blockIdx.x * blockDim.x + threadIdx.x;
    if (idx < Rr * Ee) {
        int r = idx / Ee;
        atomicAdd(&g_deg[r * Nn + dst[idx]], 1);
    }
}

// one block per relation; sequential chunked Hillis-Steele scan
__global__ void k_scan() {
    __shared__ int sh[1024];
    __shared__ int carry_s;
    int r = blockIdx.x;
    int t = threadIdx.x;
    if (t == 0) carry_s = 0;
    __syncthreads();
    for (int base = 0; base < Nn; base += 1024) {
        int i = base + t;
        int v = (i < Nn) ? g_deg[r * Nn + i] : 0;
        sh[t] = v;
        __syncthreads();
        for (int off = 1; off < 1024; off <<= 1) {
            int tv = (t >= off) ? sh[t - off] : 0;
            __syncthreads();
            sh[t] += tv;
            __syncthreads();
        }
        int excl  = sh[t] - v;
        int carry = carry_s;
        if (i < Nn) {
            g_ptr[r * (Nn + 1) + i] = carry + excl;
            g_cur[r * Nn + i]       = carry + excl;
        }
        __syncthreads();
        if (t == 1023) carry_s = carry + sh[1023];
        __syncthreads();
    }
    if (t == 0) g_ptr[r * (Nn + 1) + Nn] = carry_s;   // == Ee
}

__global__ void k_scatter(const int* __restrict__ src, const int* __restrict__ dst) {
    int idx = blockIdx.x * blockDim.x + threadIdx.x;
    if (idx < Rr * Ee) {
        int r = idx / Ee;
        int d = dst[idx];
        int pos = atomicAdd(&g_cur[r * Nn + d], 1);   // within-relation position
        g_csrc[(size_t)r * Ee + pos] = src[idx];
    }
}

// ---------------- fp32 tiled GEMM: C[M,Nc] = A[M,K] @ B[K,Nc], batched over z (relations) ----------------
__global__ __launch_bounds__(256) void gemm_f32(
    const float* __restrict__ A, const float* __restrict__ Bb, float* __restrict__ Cb,
    int M, int Nc, int K, size_t strideB, size_t strideC)
{
    __shared__ float As[16][64];
    __shared__ float Bs[16][64];
    const float* B = Bb + blockIdx.z * strideB;
    float*       C = Cb + blockIdx.z * strideC;
    int tid = threadIdx.x;
    int tx = tid & 15, ty = tid >> 4;
    int bm = blockIdx.x * 64, bn = blockIdx.y * 64;
    int arow = tid >> 2, acol = (tid & 3) << 2;
    int brow = tid >> 4, bcol = (tid & 15) << 2;
    float acc[4][4] = {};

    for (int k0 = 0; k0 < K; k0 += 16) {
        float4 av = make_float4(0.f, 0.f, 0.f, 0.f);
        if (bm + arow < M)
            av = *reinterpret_cast<const float4*>(A + (size_t)(bm + arow) * K + k0 + acol);
        As[acol + 0][arow] = av.x;
        As[acol + 1][arow] = av.y;
        As[acol + 2][arow] = av.z;
        As[acol + 3][arow] = av.w;
        *reinterpret_cast<float4*>(&Bs[brow][bcol]) =
            *reinterpret_cast<const float4*>(B + (size_t)(k0 + brow) * Nc + bn + bcol);
        __syncthreads();
#pragma unroll
        for (int kk = 0; kk < 16; kk++) {
            float a[4], b[4];
            *reinterpret_cast<float4*>(a) = *reinterpret_cast<const float4*>(&As[kk][ty << 2]);
            *reinterpret_cast<float4*>(b) = *reinterpret_cast<const float4*>(&Bs[kk][tx << 2]);
#pragma unroll
            for (int ii = 0; ii < 4; ii++)
#pragma unroll
                for (int jj = 0; jj < 4; jj++) acc[ii][jj] += a[ii] * b[jj];
        }
        __syncthreads();
    }
#pragma unroll
    for (int ii = 0; ii < 4; ii++) {
        int row = bm + (ty << 2) + ii;
        if (row < M) {
            float4 v = make_float4(acc[ii][0], acc[ii][1], acc[ii][2], acc[ii][3]);
            *reinterpret_cast<float4*>(C + (size_t)row * Nc + bn + (tx << 2)) = v;
        }
    }
}

// ---------------- el/er projections: warp per (relation, node) ----------------
template <int H, int F>
__global__ void k_elr(const float* __restrict__ hb, const float* __restrict__ al,
                      const float* __restrict__ ar, float* __restrict__ el,
                      float* __restrict__ er)
{
    const int HF = H * F, PL = HF / 32, LPH = 32 / H;
    int w    = (blockIdx.x * blockDim.x + threadIdx.x) >> 5;
    int lane = threadIdx.x & 31;
    if (w >= Rr * Nn) return;
    int r = w / Nn;
    const float* hp  = hb + (size_t)w * HF + lane * PL;
    const float* alp = al + (size_t)r * HF + lane * PL;
    const float* arp = ar + (size_t)r * HF + lane * PL;
    float sl = 0.f, sr = 0.f;
#pragma unroll
    for (int k = 0; k < PL; k++) {
        float hv = hp[k];
        sl += hv * alp[k];
        sr += hv * arp[k];
    }
#pragma unroll
    for (int off = 1; off < LPH; off <<= 1) {
        sl += __shfl_xor_sync(0xffffffffu, sl, off);
        sr += __shfl_xor_sync(0xffffffffu, sr, off);
    }
    if ((lane & (LPH - 1)) == 0) {
        int hh = lane / LPH;
        el[(size_t)w * H + hh] = sl;
        er[(size_t)w * H + hh] = sr;
    }
}

// ---------------- attention: warp per dst node ----------------
__device__ __forceinline__ void axpy8(float a, const float* __restrict__ p, float* acc) {
    float4 v0 = *reinterpret_cast<const float4*>(p);
    float4 v1 = *reinterpret_cast<const float4*>(p + 4);
    acc[0] += a * v0.x; acc[1] += a * v0.y; acc[2] += a * v0.z; acc[3] += a * v0.w;
    acc[4] += a * v1.x; acc[5] += a * v1.y; acc[6] += a * v1.z; acc[7] += a * v1.w;
}
__device__ __forceinline__ void axpy2(float a, const float* __restrict__ p, float* acc) {
    float2 v = *reinterpret_cast<const float2*>(p);
    acc[0] += a * v.x; acc[1] += a * v.y;
}

template <int H, int F, bool RELU>
__global__ void k_attn(const float* __restrict__ hb, const float* __restrict__ el,
                       const float* __restrict__ er, float* __restrict__ out)
{
    const int HF = H * F, PL = HF / 32, LPH = 32 / H;
    int w    = (blockIdx.x * blockDim.x + threadIdx.x) >> 5;
    int lane = threadIdx.x & 31;
    if (w >= Nn) return;
    const int i    = w;
    const int hidx = (lane * PL) / F;   // head owned by this lane's feature slice
    float acc[PL];
#pragma unroll
    for (int k = 0; k < PL; k++) acc[k] = 0.f;

    for (int r = 0; r < Rr; r++) {
        int s0 = g_ptr[r * (Nn + 1) + i];
        int s1 = g_ptr[r * (Nn + 1) + i + 1];
        if (s0 == s1) continue;
        float eri[H];
#pragma unroll
        for (int hh = 0; hh < H; hh++) eri[hh] = er[(size_t)(r * Nn + i) * H + hh];

        // pass 1: per-head max over in-edges
        float m[H];
#pragma unroll
        for (int hh = 0; hh < H; hh++) m[hh] = -1e30f;
        for (int j = s0 + lane; j < s1; j += 32) {
            int sn = g_csrc[(size_t)r * Ee + j];
            const float* elp = el + (size_t)(r * Nn + sn) * H;
#pragma unroll
            for (int hh = 0; hh < H; hh++) {
                float e = elp[hh] + eri[hh];
                e = (e > 0.f) ? e : 0.2f * e;
                m[hh] = fmaxf(m[hh], e);
            }
        }
#pragma unroll
        for (int hh = 0; hh < H; hh++)
#pragma unroll
            for (int off = 16; off > 0; off >>= 1)
                m[hh] = fmaxf(m[hh], __shfl_xor_sync(0xffffffffu, m[hh], off));

        // pass 2: denominator
        float den[H];
#pragma unroll
        for (int hh = 0; hh < H; hh++) den[hh] = 0.f;
        for (int j = s0 + lane; j < s1; j += 32) {
            int sn = g_csrc[(size_t)r * Ee + j];
            const float* elp = el + (size_t)(r * Nn + sn) * H;
#pragma unroll
            for (int hh = 0; hh < H; hh++) {
                float e = elp[hh] + eri[hh];
                e = (e > 0.f) ? e : 0.2f * e;
                den[hh] += __expf(e - m[hh]);
            }
        }
#pragma unroll
        for (int hh = 0; hh < H; hh++)
#pragma unroll
            for (int off = 16; off > 0; off >>= 1)
                den[hh] += __shfl_xor_sync(0xffffffffu, den[hh], off);
        float inv[H];
#pragma unroll
        for (int hh = 0; hh < H; hh++) inv[hh] = 1.f / (den[hh] + 1e-16f);

        // pass 3: weighted feature accumulation (lanes over features)
        for (int j = s0; j < s1; j++) {
            int sn = g_csrc[(size_t)r * Ee + j];
            float e = el[(size_t)(r * Nn + sn) * H + hidx] + eri[hidx];
            e = (e > 0.f) ? e : 0.2f * e;
            float alpha = __expf(e - m[hidx]) * inv[hidx];
            const float* hrow = hb + (size_t)(r * Nn + sn) * HF + lane * PL;
            if (PL == 8) axpy8(alpha, hrow, acc);
            else         axpy2(alpha, hrow, acc);
        }
    }

    // mean over heads + activation + write
#pragma unroll
    for (int k = 0; k < PL; k++) {
        float v = acc[k];
#pragma unroll
        for (int off = LPH; off < 32; off <<= 1)
            v += __shfl_xor_sync(0xffffffffu, v, off);
        v *= (1.0f / H);
        if (RELU) v = fmaxf(v, 0.f);
        if (lane < LPH) out[(size_t)i * F + lane * PL + k] = v;
    }
}

// ---------------- misc small kernels ----------------
__global__ void k_add(float* __restrict__ h1, const float* __restrict__ hx) {
    int i = blockIdx.x * blockDim.x + threadIdx.x;
    if (i < Sc * Nn * D1c) h1[i] += hx[i % (Nn * D1c)];
}

__global__ void k_rk2(const float* __restrict__ rk, float* __restrict__ out) {
    int i = threadIdx.x;
    if (i < 32) out[i] = 1.f / (1.f + __expf(-rk[i]));
}

__device__ __forceinline__ float sigf(float x) { return 1.f / (1.f + __expf(-x)); }

// ---------------- adj = mean_s sigmoid(z1[s] @ z2[s]^T) ----------------
__global__ __launch_bounds__(256) void k_adj(const float* __restrict__ mu, float* __restrict__ adj)
{
    __shared__ float Z1[Sc][32][64];   // [s][k][row]
    __shared__ float Z2[Sc][32][64];
    int tid = threadIdx.x;
    int tx = tid & 15, ty = tid >> 4;
    int bi = blockIdx.x * 64, bj = blockIdx.y * 64;
    int lrow = tid >> 2, lk = (tid & 3) << 3;

#pragma unroll
    for (int s = 0; s < Sc; s++) {
        int gi = bi + lrow;
        float4 v0 = make_float4(0.f, 0.f, 0.f, 0.f), v1 = v0;
        if (gi < N1c) {
            const float* p = mu + ((size_t)s * Nn + gi) * 32 + lk;
            v0 = *reinterpret_cast<const float4*>(p);
            v1 = *reinterpret_cast<const float4*>(p + 4);
        }
        Z1[s][lk + 0][lrow] = v0.x; Z1[s][lk + 1][lrow] = v0.y;
        Z1[s][lk + 2][lrow] = v0.z; Z1[s][lk + 3][lrow] = v0.w;
        Z1[s][lk + 4][lrow] = v1.x; Z1[s][lk + 5][lrow] = v1.y;
        Z1[s][lk + 6][lrow] = v1.z; Z1[s][lk + 7][lrow] = v1.w;

        int gj = bj + lrow;
        v0 = make_float4(0.f, 0.f, 0.f, 0.f); v1 = v0;
        if (gj < N2c) {
            const float* p = mu + ((size_t)s * Nn + N1c + gj) * 32 + lk;
            v0 = *reinterpret_cast<const float4*>(p);
            v1 = *reinterpret_cast<const float4*>(p + 4);
        }
        Z2[s][lk + 0][lrow] = v0.x; Z2[s][lk + 1][lrow] = v0.y;
        Z2[s][lk + 2][lrow] = v0.z; Z2[s][lk + 3][lrow] = v0.w;
        Z2[s][lk + 4][lrow] = v1.x; Z2[s][lk + 5][lrow] = v1.y;
        Z2[s][lk + 6][lrow] = v1.z; Z2[s][lk + 7][lrow] = v1.w;
    }
    __syncthreads();

    float acc0[4][4] = {}, acc1[4][4] = {};
#pragma unroll
    for (int k = 0; k < 32; k++) {
        float a0[4], b0[4], a1[4], b1[4];
        *reinterpret_cast<float4*>(a0) = *reinterpret_cast<const float4*>(&Z1[0][k][ty << 2]);
        *reinterpret_cast<float4*>(a1) = *reinterpret_cast<const float4*>(&Z1[1][k][ty << 2]);
        *reinterpret_cast<float4*>(b0) = *reinterpret_cast<const float4*>(&Z2[0][k][tx << 2]);
        *reinterpret_cast<float4*>(b1) = *reinterpret_cast<const float4*>(&Z2[1][k][tx << 2]);
#pragma unroll
        for (int ii = 0; ii < 4; ii++)
#pragma unroll
            for (int jj = 0; jj < 4; jj++) {
                acc0[ii][jj] += a0[ii] * b0[jj];
                acc1[ii][jj] += a1[ii] * b1[jj];
            }
    }

    bool full = (bi + 64 <= N1c) && (bj + 64 <= N2c);
#pragma unroll
    for (int ii = 0; ii < 4; ii++) {
        int row = bi + (ty << 2) + ii;
        float4 v;
        v.x = 0.5f * (sigf(acc0[ii][0]) + sigf(acc1[ii][0]));
        v.y = 0.5f * (sigf(acc0[ii][1]) + sigf(acc1[ii][1]));
        v.z = 0.5f * (sigf(acc0[ii][2]) + sigf(acc1[ii][2]));
        v.w = 0.5f * (sigf(acc0[ii][3]) + sigf(acc1[ii][3]));
        int col = bj + (tx << 2);
        if (full) {
            *reinterpret_cast<float4*>(adj + (size_t)row * N2c + col) = v;
        } else if (row < N1c) {
            if (col + 0 < N2c) adj[(size_t)row * N2c + col + 0] = v.x;
            if (col + 1 < N2c) adj[(size_t)row * N2c + col + 1] = v.y;
            if (col + 2 < N2c) adj[(size_t)row * N2c + col + 2] = v.z;
            if (col + 3 < N2c) adj[(size_t)row * N2c + col + 3] = v.w;
        }
    }
}

// ---------------- host-side orchestration ----------------
static void run_rgat(const float* X, int Din, const float* W, const float* al, const float* ar,
                     int H, bool relu, float* out,
                     float* hbuf, float* elbuf, float* erbuf)
{
    int F  = (H == 4) ? 64 : 32;
    int HF = H * F;
    dim3 g((Nn + 63) / 64, HF / 64, Rr);
    gemm_f32<<<g, 256>>>(X, W, hbuf, Nn, HF, Din, (size_t)Din * HF, (size_t)Nn * HF);
    int nb_elr = (Rr * Nn + 7) / 8;
    int nb_att = (Nn + 7) / 8;
    if (H == 4) {
        k_elr<4, 64><<<nb_elr, 256>>>(hbuf, al, ar, elbuf, erbuf);
        if (relu) k_attn<4, 64, true ><<<nb_att, 256>>>(hbuf, elbuf, erbuf, out);
        else      k_attn<4, 64, false><<<nb_att, 256>>>(hbuf, elbuf, erbuf, out);
    } else {
        k_elr<2, 32><<<nb_elr, 256>>>(hbuf, al, ar, elbuf, erbuf);
        if (relu) k_attn<2, 32, true ><<<nb_att, 256>>>(hbuf, elbuf, erbuf, out);
        else      k_attn<2, 32, false><<<nb_att, 256>>>(hbuf, elbuf, erbuf, out);
    }
}

extern "C" void kernel_launch(void* const* d_in, const int* in_sizes, int n_in,
                              void* d_out, int out_size)
{
    (void)in_sizes; (void)n_in; (void)out_size;
    const float* x     = (const float*)d_in[0];
    const float* noise = (const float*)d_in[1];
    const float* W1    = (const float*)d_in[2];
    const float* al1   = (const float*)d_in[3];
    const float* ar1   = (const float*)d_in[4];
    const float* We    = (const float*)d_in[5];
    const float* ale   = (const float*)d_in[6];
    const float* are   = (const float*)d_in[7];
    const float* W2    = (const float*)d_in[8];
    const float* al2   = (const float*)d_in[9];
    const float* ar2   = (const float*)d_in[10];
    const float* W3    = (const float*)d_in[11];
    const float* al3   = (const float*)d_in[12];
    const float* ar3   = (const float*)d_in[13];
    const float* rk    = (const float*)d_in[14];
    const int*   src   = (const int*)d_in[15];
    const int*   dst   = (const int*)d_in[16];

    // output layout: adj [1,6000,6000] | mu [S,N,32] | logvar [N,32] | rk2 [1,32]
    float* out     = (float*)d_out;
    float* out_adj = out;
    float* out_mu  = out + (size_t)N1c * N2c;
    float* out_lv  = out_mu + (size_t)Sc * Nn * D2c;
    float* out_rk  = out_lv + (size_t)Nn * D2c;

    float *hbuf, *elbuf, *erbuf, *hx, *h1;
    cudaGetSymbolAddress((void**)&hbuf,  g_h);
    cudaGetSymbolAddress((void**)&elbuf, g_el);
    cudaGetSymbolAddress((void**)&erbuf, g_er);
    cudaGetSymbolAddress((void**)&hx,    g_hiddenx);
    cudaGetSymbolAddress((void**)&h1,    g_hidden1);

    // CSR build (shared by all 6 rgat invocations)
    k_zero_deg<<<(Rr * Nn + 255) / 256, 256>>>();
    k_hist<<<(Rr * Ee + 255) / 256, 256>>>(dst);
    k_scan<<<Rr, 1024>>>();
    k_scatter<<<(Rr * Ee + 255) / 256, 256>>>(src, dst);

    // hiddenx = rgat(x, W1, ...) with relu
    run_rgat(x, HIDc, W1, al1, ar1, 4, true, hx, hbuf, elbuf, erbuf);

    // hiddene[s] = rgat(noise[s], We, ...) with relu; then hidden1 = hiddenx + hiddene
    for (int s = 0; s < Sc; s++)
        run_rgat(noise + (size_t)s * Nn * NDIMc, NDIMc, We, ale, are, 4, true,
                 h1 + (size_t)s * Nn * D1c, hbuf, elbuf, erbuf);
    k_add<<<(Sc * Nn * D1c + 255) / 256, 256>>>(h1, hx);

    // mu[s] = rgat(hidden1[s], W2, ...) identity  -> straight into d_out
    for (int s = 0; s < Sc; s++)
        run_rgat(h1 + (size_t)s * Nn * D1c, D1c, W2, al2, ar2, 2, false,
                 out_mu + (size_t)s * Nn * D2c, hbuf, elbuf, erbuf);

    // logvar = rgat(hiddenx, W3, ...) identity -> d_out
    run_rgat(hx, D1c, W3, al3, ar3, 2, false, out_lv, hbuf, elbuf, erbuf);

    // rk2 = sigmoid(rk_lgt)
    k_rk2<<<1, 32>>>(rk, out_rk);

    // adj = mean_s sigmoid(z1[s] @ z2[s]^T)
    k_adj<<<dim3((N1c + 63) / 64, (N2c + 63) / 64), 256>>>(out_mu, out_adj);
}

// round 2
// speedup vs baseline: 1.0877x; 1.0877x over previous
#include <cuda_runtime.h>

// ---------------- problem constants ----------------
#define Nn    20000
#define N1c   6000
#define N2c   6000
#define Rr    3
#define Ee    200000
#define HIDc  128
#define NDIMc 64
#define D1c   64
#define D2c   32
#define H1c   4
#define H2c   2
#define Sc    2

// ---------------- device scratch (no allocs allowed) ----------------
__device__ int   g_deg[Rr * Nn];
__device__ int   g_cur[Rr * Nn];
__device__ int   g_ptr[Rr * (Nn + 1)];
__device__ int   g_csrc[Rr * Ee];
__device__ float g_h[(size_t)6 * Nn * 256];      // batched GEMM output (max 6 inst*rel x N x 256)
__device__ float g_el[480000];
__device__ float g_er[480000];
__device__ float g_hid[3 * Nn * D1c];            // slots 0,1 = hidden1[s]; slot 2 = hiddenx

// ---------------- f32x2 helpers (FFMA2 — 2x fp32 MAC per issue slot) ----------------
__device__ __forceinline__ unsigned long long dup2(float a) {
    unsigned long long r;
    asm("mov.b64 %0, {%1, %1};" : "=l"(r) : "f"(a));
    return r;
}
__device__ __forceinline__ void ffma2(unsigned long long& d, unsigned long long a, unsigned long long b) {
    asm("fma.rn.f32x2 %0, %1, %2, %0;" : "+l"(d) : "l"(a), "l"(b));
}
__device__ __forceinline__ float2 unpk(unsigned long long v) {
    float2 f;
    asm("mov.b64 {%0, %1}, %2;" : "=f"(f.x), "=f"(f.y) : "l"(v));
    return f;
}

// ---------------- CSR build ----------------
__global__ void k_zero_deg() {
    int i = blockIdx.x * blockDim.x + threadIdx.x;
    if (i < Rr * Nn) g_deg[i] = 0;
}

__global__ void k_hist(const int* __restrict__ dst) {
    int idx = blockIdx.x * blockDim.x + threadIdx.x;
    if (idx < Rr * Ee) {
        int r = idx / Ee;
        atomicAdd(&g_deg[r * Nn + dst[idx]], 1);
    }
}

__global__ void k_scan() {
    __shared__ int sh[1024];
    __shared__ int carry_s;
    int r = blockIdx.x;
    int t = threadIdx.x;
    if (t == 0) carry_s = 0;
    __syncthreads();
    for (int base = 0; base < Nn; base += 1024) {
        int i = base + t;
        int v = (i < Nn) ? g_deg[r * Nn + i] : 0;
        sh[t] = v;
        __syncthreads();
        for (int off = 1; off < 1024; off <<= 1) {
            int tv = (t >= off) ? sh[t - off] : 0;
            __syncthreads();
            sh[t] += tv;
            __syncthreads();
        }
        int excl  = sh[t] - v;
        int carry = carry_s;
        if (i < Nn) {
            g_ptr[r * (Nn + 1) + i] = carry + excl;
            g_cur[r * Nn + i]       = carry + excl;
        }
        __syncthreads();
        if (t == 1023) carry_s = carry + sh[1023];
        __syncthreads();
    }
    if (t == 0) g_ptr[r * (Nn + 1) + Nn] = carry_s;
}

__global__ void k_scatter(const int* __restrict__ src, const int* __restrict__ dst) {
    int idx = blockIdx.x * blockDim.x + threadIdx.x;
    if (idx < Rr * Ee) {
        int r = idx / Ee;
        int d = dst[idx];
        int pos = atomicAdd(&g_cur[r * Nn + d], 1);
        g_csrc[(size_t)r * Ee + pos] = src[idx];
    }
}

// ---------------- fp32 GEMM with FFMA2: C[z] = A[inst] @ B[inst,r], z = inst*Rr + r ----------------
// BM x BN tile, 256 threads, 8x8 per thread in a 2x2 arrangement of 4x4 sub-tiles.
template<int BM, int BN, int TX>
__global__ __launch_bounds__(256) void gemm2(
    const float* __restrict__ Abase, size_t strideAinst, int K,
    const float* __restrict__ B0, const float* __restrict__ B1, const float* __restrict__ B2,
    int HF, float* __restrict__ Cbase, int M)
{
    constexpr int TY = 256 / TX;
    constexpr int BK = 16;
    __shared__ float As[BK][BM];
    __shared__ float Bs[BK][BN];
    int z = blockIdx.z;
    int r = z % Rr, inst = z / Rr;
    const float* A  = Abase + (size_t)inst * strideAinst;
    const float* Bw = (inst == 0 ? B0 : (inst == 1 ? B1 : B2)) + (size_t)r * K * HF;
    float* C = Cbase + (size_t)z * Nn * HF;
    int t = threadIdx.x;
    int tx = t % TX, ty = t / TX;
    int bm = blockIdx.x * BM, bn = blockIdx.y * BN;

    unsigned long long acc[2][4][2][2];
#pragma unroll
    for (int a = 0; a < 2; a++)
#pragma unroll
        for (int b = 0; b < 4; b++)
#pragma unroll
            for (int c = 0; c < 2; c++) { acc[a][b][c][0] = 0ull; acc[a][b][c][1] = 0ull; }

    for (int k0 = 0; k0 < K; k0 += BK) {
#pragma unroll
        for (int p = 0; p < BM * BK / 1024; p++) {
            int idx = p * 1024 + t * 4;
            int row = idx >> 4, kc = idx & 15;
            float4 v = make_float4(0.f, 0.f, 0.f, 0.f);
            if (bm + row < M)
                v = *reinterpret_cast<const float4*>(A + (size_t)(bm + row) * K + k0 + kc);
            As[kc + 0][row] = v.x; As[kc + 1][row] = v.y;
            As[kc + 2][row] = v.z; As[kc + 3][row] = v.w;
        }
#pragma unroll
        for (int p = 0; p < BN * BK / 1024; p++) {
            int idx = p * 1024 + t * 4;
            int row = idx / BN, col = idx % BN;
            *reinterpret_cast<float4*>(&Bs[row][col]) =
                *reinterpret_cast<const float4*>(Bw + (size_t)(k0 + row) * HF + bn + col);
        }
        __syncthreads();
#pragma unroll
        for (int kk = 0; kk < BK; kk++) {
            float4 av[2];
            av[0] = *reinterpret_cast<const float4*>(&As[kk][ty * 4]);
            av[1] = *reinterpret_cast<const float4*>(&As[kk][ty * 4 + TY * 4]);
            unsigned long long bv[2][2];
            {
                const unsigned long long* bp = reinterpret_cast<const unsigned long long*>(&Bs[kk][tx * 4]);
                bv[0][0] = bp[0]; bv[0][1] = bp[1];
                const unsigned long long* bq = reinterpret_cast<const unsigned long long*>(&Bs[kk][tx * 4 + TX * 4]);
                bv[1][0] = bq[0]; bv[1][1] = bq[1];
            }
#pragma unroll
            for (int rg = 0; rg < 2; rg++) {
                float ar4[4] = {av[rg].x, av[rg].y, av[rg].z, av[rg].w};
#pragma unroll
                for (int ii = 0; ii < 4; ii++) {
                    unsigned long long ad = dup2(ar4[ii]);
#pragma unroll
                    for (int cg = 0; cg < 2; cg++) {
                        ffma2(acc[rg][ii][cg][0], ad, bv[cg][0]);
                        ffma2(acc[rg][ii][cg][1], ad, bv[cg][1]);
                    }
                }
            }
        }
        __syncthreads();
    }
#pragma unroll
    for (int rg = 0; rg < 2; rg++)
#pragma unroll
        for (int ii = 0; ii < 4; ii++) {
            int row = bm + ty * 4 + rg * TY * 4 + ii;
            if (row >= M) continue;
#pragma unroll
            for (int cg = 0; cg < 2; cg++) {
                float2 lo = unpk(acc[rg][ii][cg][0]);
                float2 hi = unpk(acc[rg][ii][cg][1]);
                float4 v = make_float4(lo.x, lo.y, hi.x, hi.y);
                *reinterpret_cast<float4*>(C + (size_t)row * HF + bn + tx * 4 + cg * TX * 4) = v;
            }
        }
}

// ---------------- el/er projections: warp per (inst, relation, node) ----------------
template <int H, int F>
__global__ void k_elr(const float* __restrict__ hb,
                      const float* __restrict__ al0, const float* __restrict__ al1, const float* __restrict__ al2,
                      const float* __restrict__ ar0, const float* __restrict__ ar1, const float* __restrict__ ar2,
                      float* __restrict__ el, float* __restrict__ er, int nInst)
{
    const int HF = H * F, PL = HF / 32, LPH = 32 / H;
    int w    = (blockIdx.x * blockDim.x + threadIdx.x) >> 5;
    int lane = threadIdx.x & 31;
    if (w >= nInst * Rr * Nn) return;
    int zr = w / Nn;
    int inst = zr / Rr, r = zr % Rr;
    const float* al = (inst == 0 ? al0 : (inst == 1 ? al1 : al2));
    const float* ar = (inst == 0 ? ar0 : (inst == 1 ? ar1 : ar2));
    const float* hp  = hb + (size_t)w * HF + lane * PL;
    const float* alp = al + (size_t)r * HF + lane * PL;
    const float* arp = ar + (size_t)r * HF + lane * PL;
    float sl = 0.f, sr = 0.f;
#pragma unroll
    for (int k = 0; k < PL; k++) {
        float hv = hp[k];
        sl += hv * alp[k];
        sr += hv * arp[k];
    }
#pragma unroll
    for (int off = 1; off < LPH; off <<= 1) {
        sl += __shfl_xor_sync(0xffffffffu, sl, off);
        sr += __shfl_xor_sync(0xffffffffu, sr, off);
    }
    if ((lane & (LPH - 1)) == 0) {
        int hh = lane / LPH;
        el[(size_t)w * H + hh] = sl;
        er[(size_t)w * H + hh] = sr;
    }
}

// ---------------- attention: warp per dst node, batched over instances ----------------
template <int H, int F, bool RELU, bool ADD>
__global__ void k_attn(const float* __restrict__ hb, const float* __restrict__ elb,
                       const float* __restrict__ erb, float* __restrict__ outb,
                       long long outStride, const float* __restrict__ resid, int instBase)
{
    constexpr int HF = H * F, PL = HF / 32, LPH = 32 / H, PU = PL / 2;
    int inst = blockIdx.y + instBase;
    const float* hbi = hb  + (size_t)inst * Rr * Nn * HF;
    const float* el  = elb + (size_t)inst * Rr * Nn * H;
    const float* er  = erb + (size_t)inst * Rr * Nn * H;
    float* out = outb + (size_t)inst * outStride;

    int w    = (blockIdx.x * blockDim.x + threadIdx.x) >> 5;
    int lane = threadIdx.x & 31;
    if (w >= Nn) return;
    const int i    = w;
    const int hidx = (lane * PL) / F;
    unsigned long long acc[PU];
#pragma unroll
    for (int k = 0; k < PU; k++) acc[k] = 0ull;

    for (int r = 0; r < Rr; r++) {
        int s0 = g_ptr[r * (Nn + 1) + i];
        int s1 = g_ptr[r * (Nn + 1) + i + 1];
        if (s0 == s1) continue;
        float eri[H];
#pragma unroll
        for (int hh = 0; hh < H; hh++) eri[hh] = er[(size_t)(r * Nn + i) * H + hh];

        float m[H];
#pragma unroll
        for (int hh = 0; hh < H; hh++) m[hh] = -1e30f;
        for (int j = s0 + lane; j < s1; j += 32) {
            int sn = g_csrc[(size_t)r * Ee + j];
            const float* elp = el + (size_t)(r * Nn + sn) * H;
#pragma unroll
            for (int hh = 0; hh < H; hh++) {
                float e = elp[hh] + eri[hh];
                e = (e > 0.f) ? e : 0.2f * e;
                m[hh] = fmaxf(m[hh], e);
            }
        }
#pragma unroll
        for (int hh = 0; hh < H; hh++)
#pragma unroll
            for (int off = 16; off > 0; off >>= 1)
                m[hh] = fmaxf(m[hh], __shfl_xor_sync(0xffffffffu, m[hh], off));

        float den[H];
#pragma unroll
        for (int hh = 0; hh < H; hh++) den[hh] = 0.f;
        for (int j = s0 + lane; j < s1; j += 32) {
            int sn = g_csrc[(size_t)r * Ee + j];
            const float* elp = el + (size_t)(r * Nn + sn) * H;
#pragma unroll
            for (int hh = 0; hh < H; hh++) {
                float e = elp[hh] + eri[hh];
                e = (e > 0.f) ? e : 0.2f * e;
                den[hh] += __expf(e - m[hh]);
            }
        }
#pragma unroll
        for (int hh = 0; hh < H; hh++)
#pragma unroll
            for (int off = 16; off > 0; off >>= 1)
                den[hh] += __shfl_xor_sync(0xffffffffu, den[hh], off);
        float inv[H];
#pragma unroll
        for (int hh = 0; hh < H; hh++) inv[hh] = 1.f / (den[hh] + 1e-16f);

        for (int j = s0; j < s1; j++) {
            int sn = g_csrc[(size_t)r * Ee + j];
            float e = el[(size_t)(r * Nn + sn) * H + hidx] + eri[hidx];
            e = (e > 0.f) ? e : 0.2f * e;
            float alpha = __expf(e - m[hidx]) * inv[hidx];
            unsigned long long ad = dup2(alpha);
            const float* hrow = hbi + (size_t)(r * Nn + sn) * HF + lane * PL;
            if (PU == 4) {
                const ulonglong2* hp = reinterpret_cast<const ulonglong2*>(hrow);
                ulonglong2 h0 = hp[0], h1 = hp[1];
                ffma2(acc[0], ad, h0.x);
                ffma2(acc[1], ad, h0.y);
                ffma2(acc[2 % PU], ad, h1.x);
                ffma2(acc[3 % PU], ad, h1.y);
            } else {
                unsigned long long hv = *reinterpret_cast<const unsigned long long*>(hrow);
                ffma2(acc[0], ad, hv);
            }
        }
    }

    float af[PL];
#pragma unroll
    for (int u = 0; u < PU; u++) {
        float2 f = unpk(acc[u]);
        af[2 * u] = f.x; af[2 * u + 1] = f.y;
    }
#pragma unroll
    for (int k = 0; k < PL; k++) {
        float v = af[k];
#pragma unroll
        for (int off = LPH; off < 32; off <<= 1)
            v += __shfl_xor_sync(0xffffffffu, v, off);
        v *= (1.0f / H);
        if (RELU) v = fmaxf(v, 0.f);
        if (lane < LPH) {
            int idx = i * F + lane * PL + k;
            if (ADD) v += resid[idx];
            out[idx] = v;
        }
    }
}

// ---------------- misc ----------------
__global__ void k_rk2(const float* __restrict__ rk, float* __restrict__ out) {
    int i = threadIdx.x;
    if (i < 32) out[i] = 1.f / (1.f + __expf(-rk[i]));
}

__device__ __forceinline__ float sigf(float x) { return 1.f / (1.f + __expf(-x)); }

// ---------------- adj = mean_s sigmoid(z1[s] @ z2[s]^T), FFMA2, 128x64 tile ----------------
__global__ __launch_bounds__(256) void k_adj(const float* __restrict__ mu, float* __restrict__ adj)
{
    __shared__ float Z1t[Sc][16][132];   // [s][k-half][row], padded
    __shared__ float Z2t[Sc][32][68];    // [s][k][col], padded
    int t = threadIdx.x;
    int tx = t & 15, ty = t >> 4;
    int bi = blockIdx.x * 128, bj = blockIdx.y * 64;

    // load Z2 (full K=32), transposed
#pragma unroll
    for (int s = 0; s < Sc; s++)
#pragma unroll
        for (int p = 0; p < 2; p++) {
            int idx = p * 1024 + t * 4;
            int j = idx >> 5, kc = idx & 31;
            float4 v = make_float4(0.f, 0.f, 0.f, 0.f);
            int gj = bj + j;
            if (gj < N2c)
                v = *reinterpret_cast<const float4*>(mu + ((size_t)s * Nn + N1c + gj) * 32 + kc);
            Z2t[s][kc + 0][j] = v.x; Z2t[s][kc + 1][j] = v.y;
            Z2t[s][kc + 2][j] = v.z; Z2t[s][kc + 3][j] = v.w;
        }

    unsigned long long acc[Sc][4][4];
#pragma unroll
    for (int s = 0; s < Sc; s++)
#pragma unroll
        for (int a = 0; a < 4; a++)
#pragma unroll
            for (int b = 0; b < 4; b++) acc[s][a][b] = 0ull;

#pragma unroll
    for (int h = 0; h < 2; h++) {
        __syncthreads();
#pragma unroll
        for (int s = 0; s < Sc; s++)
#pragma unroll
            for (int p = 0; p < 2; p++) {
                int idx = p * 1024 + t * 4;
                int row = idx >> 4, kc = idx & 15;
                float4 v = make_float4(0.f, 0.f, 0.f, 0.f);
                int gi = bi + row;
                if (gi < N1c)
                    v = *reinterpret_cast<const float4*>(mu + ((size_t)s * Nn + gi) * 32 + h * 16 + kc);
                Z1t[s][kc + 0][row] = v.x; Z1t[s][kc + 1][row] = v.y;
                Z1t[s][kc + 2][row] = v.z; Z1t[s][kc + 3][row] = v.w;
            }
        __syncthreads();
#pragma unroll
        for (int kk = 0; kk < 16; kk++)
#pragma unroll
            for (int s = 0; s < Sc; s++) {
                const ulonglong2* ap = reinterpret_cast<const ulonglong2*>(&Z1t[s][kk][ty * 8]);
                ulonglong2 A0 = ap[0], A1 = ap[1];
                unsigned long long au[4] = {A0.x, A0.y, A1.x, A1.y};
                float4 b4 = *reinterpret_cast<const float4*>(&Z2t[s][h * 16 + kk][tx * 4]);
                float bs[4] = {b4.x, b4.y, b4.z, b4.w};
#pragma unroll
                for (int jj = 0; jj < 4; jj++) {
                    unsigned long long bd = dup2(bs[jj]);
#pragma unroll
                    for (int rp = 0; rp < 4; rp++) ffma2(acc[s][rp][jj], au[rp], bd);
                }
            }
    }

    int col = bj + tx * 4;
    if (col >= N2c) return;
#pragma unroll
    for (int rp = 0; rp < 4; rp++) {
        float4 ve, vo;
        float* pe = &ve.x; float* po = &vo.x;
#pragma unroll
        for (int jj = 0; jj < 4; jj++) {
            float2 f0 = unpk(acc[0][rp][jj]);
            float2 f1 = unpk(acc[1][rp][jj]);
            pe[jj] = 0.5f * (sigf(f0.x) + sigf(f1.x));
            po[jj] = 0.5f * (sigf(f0.y) + sigf(f1.y));
        }
        int row0 = bi + ty * 8 + rp * 2;
        if (row0 < N1c)
            *reinterpret_cast<float4*>(adj + (size_t)row0 * N2c + col) = ve;
        if (row0 + 1 < N1c)
            *reinterpret_cast<float4*>(adj + (size_t)(row0 + 1) * N2c + col) = vo;
    }
}

// ---------------- host-side orchestration ----------------
extern "C" void kernel_launch(void* const* d_in, const int* in_sizes, int n_in,
                              void* d_out, int out_size)
{
    (void)in_sizes; (void)n_in; (void)out_size;
    const float* x     = (const float*)d_in[0];
    const float* noise = (const float*)d_in[1];
    const float* W1    = (const float*)d_in[2];
    const float* al1   = (const float*)d_in[3];
    const float* ar1   = (const float*)d_in[4];
    const float* We    = (const float*)d_in[5];
    const float* ale   = (const float*)d_in[6];
    const float* are   = (const float*)d_in[7];
    const float* W2    = (const float*)d_in[8];
    const float* al2   = (const float*)d_in[9];
    const float* ar2   = (const float*)d_in[10];
    const float* W3    = (const float*)d_in[11];
    const float* al3   = (const float*)d_in[12];
    const float* ar3   = (const float*)d_in[13];
    const float* rk    = (const float*)d_in[14];
    const int*   src   = (const int*)d_in[15];
    const int*   dst   = (const int*)d_in[16];

    float* out     = (float*)d_out;
    float* out_adj = out;
    float* out_mu  = out + (size_t)N1c * N2c;
    float* out_lv  = out_mu + (size_t)Sc * Nn * D2c;
    float* out_rk  = out_lv + (size_t)Nn * D2c;

    float *hbuf, *elbuf, *erbuf, *hid;
    cudaGetSymbolAddress((void**)&hbuf,  g_h);
    cudaGetSymbolAddress((void**)&elbuf, g_el);
    cudaGetSymbolAddress((void**)&erbuf, g_er);
    cudaGetSymbolAddress((void**)&hid,   g_hid);
    float* hx = hid + (size_t)2 * Nn * D1c;

    // ---- CSR (shared by all 6 rgat layers) ----
    k_zero_deg<<<(Rr * Nn + 255) / 256, 256>>>();
    k_hist<<<(Rr * Ee + 255) / 256, 256>>>(dst);
    k_scan<<<Rr, 1024>>>();
    k_scatter<<<(Rr * Ee + 255) / 256, 256>>>(src, dst);

    // ---- layer x: hiddenx = rgat(x, W1, relu) ----
    gemm2<128, 128, 16><<<dim3(157, 2, 3), 256>>>(x, 0, HIDc, W1, W1, W1, 256, hbuf, Nn);
    k_elr<4, 64><<<(1 * Rr * Nn * 32 + 255) / 256, 256>>>(hbuf, al1, al1, al1, ar1, ar1, ar1, elbuf, erbuf, 1);
    k_attn<4, 64, true, false><<<dim3((Nn + 7) / 8, 1), 256>>>(hbuf, elbuf, erbuf, hx, 0, nullptr, 0);

    // ---- noise layers: hidden1[s] = hiddenx + rgat(noise[s], We, relu) ----
    gemm2<128, 128, 16><<<dim3(157, 2, 6), 256>>>(noise, (size_t)Nn * NDIMc, NDIMc, We, We, We, 256, hbuf, Nn);
    k_elr<4, 64><<<(2 * Rr * Nn * 32 + 255) / 256, 256>>>(hbuf, ale, ale, ale, are, are, are, elbuf, erbuf, 2);
    k_attn<4, 64, true, true><<<dim3((Nn + 7) / 8, 1), 256>>>(hbuf, elbuf, erbuf, hid, (long long)Nn * D1c, hx, 0);
    k_attn<4, 64, true, true><<<dim3((Nn + 7) / 8, 1), 256>>>(hbuf, elbuf, erbuf, hid, (long long)Nn * D1c, hx, 1);

    // ---- mu[0], mu[1], logvar: batched (inst 0,1 use W2 on hidden1; inst 2 uses W3 on hiddenx) ----
    gemm2<256, 64, 8><<<dim3(79, 1, 9), 256>>>(hid, (size_t)Nn * D1c, D1c, W2, W2, W3, 64, hbuf, Nn);
    k_elr<2, 32><<<(3 * Rr * Nn * 32 + 255) / 256, 256>>>(hbuf, al2, al2, al3, ar2, ar2, ar3, elbuf, erbuf, 3);
    k_attn<2, 32, false, false><<<dim3((Nn + 7) / 8, 3), 256>>>(hbuf, elbuf, erbuf, out_mu, (long long)Nn * D2c, nullptr, 0);

    // ---- rk2 = sigmoid(rk_lgt) ----
    k_rk2<<<1, 32>>>(rk, out_rk);

    // ---- adj = mean_s sigmoid(z1[s] @ z2[s]^T) ----
    k_adj<<<dim3((N1c + 127) / 128, (N2c + 63) / 64), 256>>>(out_mu, out_adj);
}

// round 4
// speedup vs baseline: 1.3031x; 1.1980x over previous
#include <cuda_runtime.h>
#include <cstdint>

// ---------------- problem constants ----------------
#define Nn    20000
#define N1c   6000
#define N2c   6000
#define Rr    3
#define Ee    200000
#define HIDc  128
#define NDIMc 64
#define D1c   64
#define D2c   32
#define Sc    2

// ---------------- device scratch ----------------
__device__ int   g_deg[Rr * Nn];
__device__ int   g_cur[Rr * Nn];
__device__ int   g_ptr[Rr * (Nn + 1)];
__device__ int   g_csrc[Rr * Ee];
__device__ float g_h[(size_t)6 * Nn * 256];
__device__ float g_el[480000];
__device__ float g_er[480000];
__device__ float g_hid[3 * Nn * D1c];   // slots 0,1 = hidden1[s]; slot 2 = hiddenx

// ---------------- f32x2 helpers (attention) ----------------
__device__ __forceinline__ unsigned long long dup2(float a) {
    unsigned long long r;
    asm("mov.b64 %0, {%1, %1};" : "=l"(r) : "f"(a));
    return r;
}
__device__ __forceinline__ void ffma2(unsigned long long& d, unsigned long long a, unsigned long long b) {
    asm("fma.rn.f32x2 %0, %1, %2, %0;" : "+l"(d) : "l"(a), "l"(b));
}
__device__ __forceinline__ float2 unpk(unsigned long long v) {
    float2 f;
    asm("mov.b64 {%0, %1}, %2;" : "=f"(f.x), "=f"(f.y) : "l"(v));
    return f;
}

// ---------------- tf32 mma helpers ----------------
__device__ __forceinline__ uint32_t f2tf(float f) {
    uint32_t r;
    asm("cvt.rna.tf32.f32 %0, %1;" : "=r"(r) : "f"(f));
    return r;
}
__device__ __forceinline__ uint32_t sptr(const void* p) {
    return (uint32_t)__cvta_generic_to_shared(p);
}
__device__ __forceinline__ void ldsm_x4(uint32_t& r0, uint32_t& r1, uint32_t& r2, uint32_t& r3, uint32_t a) {
    asm volatile("ldmatrix.sync.aligned.m8n8.x4.shared.b16 {%0,%1,%2,%3}, [%4];"
                 : "=r"(r0), "=r"(r1), "=r"(r2), "=r"(r3) : "r"(a));
}
__device__ __forceinline__ void ldsm_x2(uint32_t& r0, uint32_t& r1, uint32_t a) {
    asm volatile("ldmatrix.sync.aligned.m8n8.x2.shared.b16 {%0,%1}, [%2];"
                 : "=r"(r0), "=r"(r1) : "r"(a));
}
__device__ __forceinline__ void mma_tf32(float c[4], const uint32_t a[4], const uint32_t b[2]) {
    asm volatile("mma.sync.aligned.m16n8k8.row.col.f32.tf32.tf32.f32 "
                 "{%0,%1,%2,%3},{%4,%5,%6,%7},{%8,%9},{%0,%1,%2,%3};"
                 : "+f"(c[0]), "+f"(c[1]), "+f"(c[2]), "+f"(c[3])
                 : "r"(a[0]), "r"(a[1]), "r"(a[2]), "r"(a[3]), "r"(b[0]), "r"(b[1]));
}

// ---------------- CSR build ----------------
__global__ void k_zero_deg() {
    int i = blockIdx.x * blockDim.x + threadIdx.x;
    if (i < Rr * Nn) g_deg[i] = 0;
}

__global__ void k_hist(const int* __restrict__ dst) {
    int idx = blockIdx.x * blockDim.x + threadIdx.x;
    if (idx < Rr * Ee) {
        int r = idx / Ee;
        atomicAdd(&g_deg[r * Nn + dst[idx]], 1);
    }
}

__global__ void k_scan() {
    __shared__ int sums[32];
    __shared__ int carry_s;
    int r = blockIdx.x;
    int t = threadIdx.x;
    int lane = t & 31, warp = t >> 5;
    if (t == 0) carry_s = 0;
    __syncthreads();
    for (int base = 0; base < Nn; base += 1024) {
        int carry = carry_s;
        int i = base + t;
        int v = (i < Nn) ? g_deg[r * Nn + i] : 0;
        int inc = v;
#pragma unroll
        for (int off = 1; off < 32; off <<= 1) {
            int n = __shfl_up_sync(0xffffffffu, inc, off);
            if (lane >= off) inc += n;
        }
        if (lane == 31) sums[warp] = inc;
        __syncthreads();
        if (warp == 0) {
            int s = sums[lane];
#pragma unroll
            for (int off = 1; off < 32; off <<= 1) {
                int n = __shfl_up_sync(0xffffffffu, s, off);
                if (lane >= off) s += n;
            }
            sums[lane] = s;
        }
        __syncthreads();
        int woff = (warp > 0) ? sums[warp - 1] : 0;
        int total = carry + woff + inc;
        if (i < Nn) {
            g_ptr[r * (Nn + 1) + i] = total - v;
            g_cur[r * Nn + i]       = total - v;
        }
        __syncthreads();
        if (t == 1023) carry_s = total;
        __syncthreads();
    }
    if (t == 0) g_ptr[r * (Nn + 1) + Nn] = carry_s;
}

__global__ void k_scatter(const int* __restrict__ src, const int* __restrict__ dst) {
    int idx = blockIdx.x * blockDim.x + threadIdx.x;
    if (idx < Rr * Ee) {
        int r = idx / Ee;
        int d = dst[idx];
        int pos = atomicAdd(&g_cur[r * Nn + d], 1);
        g_csrc[(size_t)r * Ee + pos] = src[idx];
    }
}

// ---------------- tf32 mma GEMM: C[z] = A[inst] @ B[inst,r], z = inst*Rr + r ----------------
// BM=128, BK=32, 256 threads (8 warps as 4m x 2n). BN = 128 or 64.
template<int BN>
__global__ __launch_bounds__(256) void gemm_mma(
    const float* __restrict__ Abase, size_t strideAinst, int K,
    const float* __restrict__ B0, const float* __restrict__ B1, const float* __restrict__ B2,
    int HF, float* __restrict__ Cbase, int M)
{
    constexpr int RS = 36;                 // row stride in floats (144B = 9 x 16B granules)
    constexpr int WN = BN / 2;
    constexpr int NT = WN / 8;
    __shared__ __align__(16) uint32_t As[128 * RS];
    __shared__ __align__(16) uint32_t Bs[BN * RS];

    int z = blockIdx.z;
    int r = z % Rr, inst = z / Rr;
    const float* A  = Abase + (size_t)inst * strideAinst;
    const float* Bw = (inst == 0 ? B0 : (inst == 1 ? B1 : B2)) + (size_t)r * K * HF;
    float* C = Cbase + (size_t)z * Nn * HF;

    int t = threadIdx.x;
    int lane = t & 31, warp = t >> 5;
    int warp_m = warp & 3, warp_n = warp >> 2;
    int bm = blockIdx.x * 128, bn = blockIdx.y * BN;

    float c[2][NT][4];
#pragma unroll
    for (int mt = 0; mt < 2; mt++)
#pragma unroll
        for (int nt = 0; nt < NT; nt++)
#pragma unroll
            for (int q = 0; q < 4; q++) c[mt][nt][q] = 0.f;

    for (int k0 = 0; k0 < K; k0 += 32) {
        // A tile: 128x32 -> 4 float4 per thread
#pragma unroll
        for (int p = 0; p < 4; p++) {
            int fid = p * 256 + t;
            int row = fid >> 3, g = fid & 7;
            float4 v = make_float4(0.f, 0.f, 0.f, 0.f);
            if (bm + row < M)
                v = *reinterpret_cast<const float4*>(A + (size_t)(bm + row) * K + k0 + g * 4);
            uint32_t* d = &As[row * RS + g * 4];
            d[0] = f2tf(v.x); d[1] = f2tf(v.y); d[2] = f2tf(v.z); d[3] = f2tf(v.w);
        }
        // B tile: 32 x BN, stored transposed [n][k]  (BN*32/1024 = BN/32 passes)
#pragma unroll
        for (int p = 0; p < BN / 32; p++) {
            int fid = p * 256 + t;
            int k = fid / (BN / 4), n = (fid % (BN / 4)) * 4;
            float4 v = *reinterpret_cast<const float4*>(Bw + (size_t)(k0 + k) * HF + bn + n);
            Bs[(n + 0) * RS + k] = f2tf(v.x);
            Bs[(n + 1) * RS + k] = f2tf(v.y);
            Bs[(n + 2) * RS + k] = f2tf(v.z);
            Bs[(n + 3) * RS + k] = f2tf(v.w);
        }
        __syncthreads();
#pragma unroll
        for (int ks = 0; ks < 4; ks++) {
            uint32_t a[2][4];
#pragma unroll
            for (int mt = 0; mt < 2; mt++) {
                int rr = warp_m * 32 + mt * 16 + (lane & 7) + ((lane >> 3) & 1) * 8;
                int gg = ks * 2 + (lane >> 4);
                ldsm_x4(a[mt][0], a[mt][1], a[mt][2], a[mt][3], sptr(&As[rr * RS + gg * 4]));
            }
            uint32_t b[NT][2];
#pragma unroll
            for (int nt = 0; nt < NT; nt++) {
                int rB = warp_n * WN + nt * 8 + (lane & 7);
                int gB = ks * 2 + ((lane >> 3) & 1);
                ldsm_x2(b[nt][0], b[nt][1], sptr(&Bs[rB * RS + gB * 4]));
            }
#pragma unroll
            for (int mt = 0; mt < 2; mt++)
#pragma unroll
                for (int nt = 0; nt < NT; nt++) mma_tf32(c[mt][nt], a[mt], b[nt]);
        }
        __syncthreads();
    }

#pragma unroll
    for (int mt = 0; mt < 2; mt++)
#pragma unroll
        for (int nt = 0; nt < NT; nt++) {
            int row0 = bm + warp_m * 32 + mt * 16 + (lane >> 2);
            int col  = bn + warp_n * WN + nt * 8 + (lane & 3) * 2;
            if (row0 < M)
                *reinterpret_cast<float2*>(C + (size_t)row0 * HF + col) = make_float2(c[mt][nt][0], c[mt][nt][1]);
            if (row0 + 8 < M)
                *reinterpret_cast<float2*>(C + (size_t)(row0 + 8) * HF + col) = make_float2(c[mt][nt][2], c[mt][nt][3]);
        }
}

// ---------------- el/er projections: warp per (inst, relation, node) ----------------
template <int H, int F>
__global__ void k_elr(const float* __restrict__ hb,
                      const float* __restrict__ al0, const float* __restrict__ al1, const float* __restrict__ al2,
                      const float* __restrict__ ar0, const float* __restrict__ ar1, const float* __restrict__ ar2,
                      float* __restrict__ el, float* __restrict__ er, int nInst)
{
    const int HF = H * F, PL = HF / 32, LPH = 32 / H;
    int w    = (blockIdx.x * blockDim.x + threadIdx.x) >> 5;
    int lane = threadIdx.x & 31;
    if (w >= nInst * Rr * Nn) return;
    int zr = w / Nn;
    int inst = zr / Rr, r = zr % Rr;
    const float* al = (inst == 0 ? al0 : (inst == 1 ? al1 : al2));
    const float* ar = (inst == 0 ? ar0 : (inst == 1 ? ar1 : ar2));
    const float* hp  = hb + (size_t)w * HF + lane * PL;
    const float* alp = al + (size_t)r * HF + lane * PL;
    const float* arp = ar + (size_t)r * HF + lane * PL;
    float sl = 0.f, sr = 0.f;
#pragma unroll
    for (int k = 0; k < PL; k++) {
        float hv = hp[k];
        sl += hv * alp[k];
        sr += hv * arp[k];
    }
#pragma unroll
    for (int off = 1; off < LPH; off <<= 1) {
        sl += __shfl_xor_sync(0xffffffffu, sl, off);
        sr += __shfl_xor_sync(0xffffffffu, sr, off);
    }
    if ((lane & (LPH - 1)) == 0) {
        int hh = lane / LPH;
        el[(size_t)w * H + hh] = sl;
        er[(size_t)w * H + hh] = sr;
    }
}

// ---------------- attention: warp per dst node, batched over instances ----------------
template <int H, int F, bool RELU, bool ADD>
__global__ void k_attn(const float* __restrict__ hb, const float* __restrict__ elb,
                       const float* __restrict__ erb, float* __restrict__ outb,
                       long long outStride, const float* __restrict__ resid, int instBase)
{
    constexpr int HF = H * F, PL = HF / 32, LPH = 32 / H, PU = PL / 2;
    int inst = blockIdx.y + instBase;
    const float* hbi = hb  + (size_t)inst * Rr * Nn * HF;
    const float* el  = elb + (size_t)inst * Rr * Nn * H;
    const float* er  = erb + (size_t)inst * Rr * Nn * H;
    float* out = outb + (size_t)inst * outStride;

    int w    = (blockIdx.x * blockDim.x + threadIdx.x) >> 5;
    int lane = threadIdx.x & 31;
    if (w >= Nn) return;
    const int i    = w;
    const int hidx = (lane * PL) / F;
    unsigned long long acc[PU];
#pragma unroll
    for (int k = 0; k < PU; k++) acc[k] = 0ull;

    for (int r = 0; r < Rr; r++) {
        int s0 = g_ptr[r * (Nn + 1) + i];
        int s1 = g_ptr[r * (Nn + 1) + i + 1];
        if (s0 == s1) continue;
        float eri[H];
#pragma unroll
        for (int hh = 0; hh < H; hh++) eri[hh] = er[(size_t)(r * Nn + i) * H + hh];

        float m[H];
#pragma unroll
        for (int hh = 0; hh < H; hh++) m[hh] = -1e30f;
        for (int j = s0 + lane; j < s1; j += 32) {
            int sn = g_csrc[(size_t)r * Ee + j];
            const float* elp = el + (size_t)(r * Nn + sn) * H;
#pragma unroll
            for (int hh = 0; hh < H; hh++) {
                float e = elp[hh] + eri[hh];
                e = (e > 0.f) ? e : 0.2f * e;
                m[hh] = fmaxf(m[hh], e);
            }
        }
#pragma unroll
        for (int hh = 0; hh < H; hh++)
#pragma unroll
            for (int off = 16; off > 0; off >>= 1)
                m[hh] = fmaxf(m[hh], __shfl_xor_sync(0xffffffffu, m[hh], off));

        float den[H];
#pragma unroll
        for (int hh = 0; hh < H; hh++) den[hh] = 0.f;
        for (int j = s0 + lane; j < s1; j += 32) {
            int sn = g_csrc[(size_t)r * Ee + j];
            const float* elp = el + (size_t)(r * Nn + sn) * H;
#pragma unroll
            for (int hh = 0; hh < H; hh++) {
                float e = elp[hh] + eri[hh];
                e = (e > 0.f) ? e : 0.2f * e;
                den[hh] += __expf(e - m[hh]);
            }
        }
#pragma unroll
        for (int hh = 0; hh < H; hh++)
#pragma unroll
            for (int off = 16; off > 0; off >>= 1)
                den[hh] += __shfl_xor_sync(0xffffffffu, den[hh], off);
        float inv[H];
#pragma unroll
        for (int hh = 0; hh < H; hh++) inv[hh] = 1.f / (den[hh] + 1e-16f);

        for (int j = s0; j < s1; j++) {
            int sn = g_csrc[(size_t)r * Ee + j];
            float e = el[(size_t)(r * Nn + sn) * H + hidx] + eri[hidx];
            e = (e > 0.f) ? e : 0.2f * e;
            float alpha = __expf(e - m[hidx]) * inv[hidx];
            unsigned long long ad = dup2(alpha);
            const float* hrow = hbi + (size_t)(r * Nn + sn) * HF + lane * PL;
            if (PU == 4) {
                const ulonglong2* hp = reinterpret_cast<const ulonglong2*>(hrow);
                ulonglong2 h0 = hp[0], h1 = hp[1];
                ffma2(acc[0], ad, h0.x);
                ffma2(acc[1], ad, h0.y);
                ffma2(acc[2 % PU], ad, h1.x);
                ffma2(acc[3 % PU], ad, h1.y);
            } else {
                unsigned long long hv = *reinterpret_cast<const unsigned long long*>(hrow);
                ffma2(acc[0], ad, hv);
            }
        }
    }

    float af[PL];
#pragma unroll
    for (int u = 0; u < PU; u++) {
        float2 f = unpk(acc[u]);
        af[2 * u] = f.x; af[2 * u + 1] = f.y;
    }
#pragma unroll
    for (int k = 0; k < PL; k++) {
        float v = af[k];
#pragma unroll
        for (int off = LPH; off < 32; off <<= 1)
            v += __shfl_xor_sync(0xffffffffu, v, off);
        v *= (1.0f / H);
        if (RELU) v = fmaxf(v, 0.f);
        if (lane < LPH) {
            int idx = i * F + lane * PL + k;
            if (ADD) v += resid[idx];
            out[idx] = v;
        }
    }
}

// ---------------- misc ----------------
__global__ void k_rk2(const float* __restrict__ rk, float* __restrict__ out) {
    int i = threadIdx.x;
    if (i < 32) out[i] = 1.f / (1.f + __expf(-rk[i]));
}

__device__ __forceinline__ float sigf(float x) { return 1.f / (1.f + __expf(-x)); }

// ---------------- adj = mean_s sigmoid(z1[s] @ z2[s]^T), tf32 mma, 64x64 tile ----------------
__global__ __launch_bounds__(256) void k_adj_mma(const float* __restrict__ mu, float* __restrict__ adj)
{
    constexpr int RS = 36;
    __shared__ __align__(16) uint32_t Z1s[Sc][64 * RS];
    __shared__ __align__(16) uint32_t Z2s[Sc][64 * RS];
    int t = threadIdx.x;
    int lane = t & 31, warp = t >> 5;
    int warp_m = warp & 1, warp_n = warp >> 1;   // 2m x 4n; WM=32, WN=16, MT=2, NT=2
    int bi = blockIdx.x * 64, bj = blockIdx.y * 64;

#pragma unroll
    for (int s = 0; s < Sc; s++) {
#pragma unroll
        for (int p = 0; p < 2; p++) {
            int fid = p * 256 + t;
            int row = fid >> 3, g = fid & 7;
            float4 v = make_float4(0.f, 0.f, 0.f, 0.f);
            if (bi + row < N1c)
                v = *reinterpret_cast<const float4*>(mu + ((size_t)s * Nn + bi + row) * 32 + g * 4);
            uint32_t* d = &Z1s[s][row * RS + g * 4];
            d[0] = f2tf(v.x); d[1] = f2tf(v.y); d[2] = f2tf(v.z); d[3] = f2tf(v.w);
            v = make_float4(0.f, 0.f, 0.f, 0.f);
            if (bj + row < N2c)
                v = *reinterpret_cast<const float4*>(mu + ((size_t)s * Nn + N1c + bj + row) * 32 + g * 4);
            d = &Z2s[s][row * RS + g * 4];
            d[0] = f2tf(v.x); d[1] = f2tf(v.y); d[2] = f2tf(v.z); d[3] = f2tf(v.w);
        }
    }
    __syncthreads();

    float c[Sc][2][2][4];
#pragma unroll
    for (int s = 0; s < Sc; s++)
#pragma unroll
        for (int mt = 0; mt < 2; mt++)
#pragma unroll
            for (int nt = 0; nt < 2; nt++)
#pragma unroll
                for (int q = 0; q < 4; q++) c[s][mt][nt][q] = 0.f;

#pragma unroll
    for (int ks = 0; ks < 4; ks++) {
#pragma unroll
        for (int s = 0; s < Sc; s++) {
            uint32_t a[2][4];
#pragma unroll
            for (int mt = 0; mt < 2; mt++) {
                int rr = warp_m * 32 + mt * 16 + (lane & 7) + ((lane >> 3) & 1) * 8;
                int gg = ks * 2 + (lane >> 4);
                ldsm_x4(a[mt][0], a[mt][1], a[mt][2], a[mt][3], sptr(&Z1s[s][rr * RS + gg * 4]));
            }
            uint32_t b[2][2];
#pragma unroll
            for (int nt = 0; nt < 2; nt++) {
                int rB = warp_n * 16 + nt * 8 + (lane & 7);
                int gB = ks * 2 + ((lane >> 3) & 1);
                ldsm_x2(b[nt][0], b[nt][1], sptr(&Z2s[s][rB * RS + gB * 4]));
            }
#pragma unroll
            for (int mt = 0; mt < 2; mt++)
#pragma unroll
                for (int nt = 0; nt < 2; nt++) mma_tf32(c[s][mt][nt], a[mt], b[nt]);
        }
    }

#pragma unroll
    for (int mt = 0; mt < 2; mt++)
#pragma unroll
        for (int nt = 0; nt < 2; nt++) {
            int row0 = bi + warp_m * 32 + mt * 16 + (lane >> 2);
            int col  = bj + warp_n * 16 + nt * 8 + (lane & 3) * 2;
            if (col >= N2c) continue;
            if (row0 < N1c) {
                float2 v = make_float2(0.5f * (sigf(c[0][mt][nt][0]) + sigf(c[1][mt][nt][0])),
                                       0.5f * (sigf(c[0][mt][nt][1]) + sigf(c[1][mt][nt][1])));
                *reinterpret_cast<float2*>(adj + (size_t)row0 * N2c + col) = v;
            }
            if (row0 + 8 < N1c) {
                float2 v = make_float2(0.5f * (sigf(c[0][mt][nt][2]) + sigf(c[1][mt][nt][2])),
                                       0.5f * (sigf(c[0][mt][nt][3]) + sigf(c[1][mt][nt][3])));
                *reinterpret_cast<float2*>(adj + (size_t)(row0 + 8) * N2c + col) = v;
            }
        }
}

// ---------------- host-side orchestration ----------------
extern "C" void kernel_launch(void* const* d_in, const int* in_sizes, int n_in,
                              void* d_out, int out_size)
{
    (void)in_sizes; (void)n_in; (void)out_size;
    const float* x     = (const float*)d_in[0];
    const float* noise = (const float*)d_in[1];
    const float* W1    = (const float*)d_in[2];
    const float* al1   = (const float*)d_in[3];
    const float* ar1   = (const float*)d_in[4];
    const float* We    = (const float*)d_in[5];
    const float* ale   = (const float*)d_in[6];
    const float* are   = (const float*)d_in[7];
    const float* W2    = (const float*)d_in[8];
    const float* al2   = (const float*)d_in[9];
    const float* ar2   = (const float*)d_in[10];
    const float* W3    = (const float*)d_in[11];
    const float* al3   = (const float*)d_in[12];
    const float* ar3   = (const float*)d_in[13];
    const float* rk    = (const float*)d_in[14];
    const int*   src   = (const int*)d_in[15];
    const int*   dst   = (const int*)d_in[16];

    float* out     = (float*)d_out;
    float* out_adj = out;
    float* out_mu  = out + (size_t)N1c * N2c;
    float* out_lv  = out_mu + (size_t)Sc * Nn * D2c;
    float* out_rk  = out_lv + (size_t)Nn * D2c;

    float *hbuf, *elbuf, *erbuf, *hid;
    cudaGetSymbolAddress((void**)&hbuf,  g_h);
    cudaGetSymbolAddress((void**)&elbuf, g_el);
    cudaGetSymbolAddress((void**)&erbuf, g_er);
    cudaGetSymbolAddress((void**)&hid,   g_hid);
    float* hx = hid + (size_t)2 * Nn * D1c;

    // ---- CSR (shared by all 6 rgat layers) ----
    k_zero_deg<<<(Rr * Nn + 255) / 256, 256>>>();
    k_hist<<<(Rr * Ee + 255) / 256, 256>>>(dst);
    k_scan<<<Rr, 1024>>>();
    k_scatter<<<(Rr * Ee + 255) / 256, 256>>>(src, dst);

    // ---- layer x: hiddenx = rgat(x, W1, relu) ----
    gemm_mma<128><<<dim3(157, 2, 3), 256>>>(x, 0, HIDc, W1, W1, W1, 256, hbuf, Nn);
    k_elr<4, 64><<<(1 * Rr * Nn * 32 + 255) / 256, 256>>>(hbuf, al1, al1, al1, ar1, ar1, ar1, elbuf, erbuf, 1);
    k_attn<4, 64, true, false><<<dim3((Nn + 7) / 8, 1), 256>>>(hbuf, elbuf, erbuf, hx, 0, nullptr, 0);

    // ---- noise layers: hidden1[s] = hiddenx + rgat(noise[s], We, relu) ----
    gemm_mma<128><<<dim3(157, 2, 6), 256>>>(noise, (size_t)Nn * NDIMc, NDIMc, We, We, We, 256, hbuf, Nn);
    k_elr<4, 64><<<(2 * Rr * Nn * 32 + 255) / 256, 256>>>(hbuf, ale, ale, ale, are, are, are, elbuf, erbuf, 2);
    k_attn<4, 64, true, true><<<dim3((Nn + 7) / 8, 2), 256>>>(hbuf, elbuf, erbuf, hid, (long long)Nn * D1c, hx, 0);

    // ---- mu[0], mu[1], logvar: batched ----
    gemm_mma<64><<<dim3(157, 1, 9), 256>>>(hid, (size_t)Nn * D1c, D1c, W2, W2, W3, 64, hbuf, Nn);
    k_elr<2, 32><<<(3 * Rr * Nn * 32 + 255) / 256, 256>>>(hbuf, al2, al2, al3, ar2, ar2, ar3, elbuf, erbuf, 3);
    k_attn<2, 32, false, false><<<dim3((Nn + 7) / 8, 3), 256>>>(hbuf, elbuf, erbuf, out_mu, (long long)Nn * D2c, nullptr, 0);

    // ---- rk2 = sigmoid(rk_lgt) ----
    k_rk2<<<1, 32>>>(rk, out_rk);

    // ---- adj = mean_s sigmoid(z1[s] @ z2[s]^T) ----
    k_adj_mma<<<dim3((N1c + 63) / 64, (N2c + 63) / 64), 256>>>(out_mu, out_adj);
}